// round 8
// baseline (speedup 1.0000x reference)
#include <cuda_runtime.h>
#include <cuda_fp16.h>
#include <math.h>

#define N_NODES 200000
#define HDIM 8
#define FIN 64
#define ROWB 32     // packed src row: 16B fp16 h + 4B fp32 as + 12B pad

// ---------------- packed parameter block (constant + staging) ----------------
struct CParams {               // field order == gather segment order (all float)
    float W[3][FIN * HDIM];    // 3 x 512
    float b[3][HDIM];
    float attSrc[4][HDIM];     // t0..t3
    float attDst[4][HDIM];
    float kW[HDIM * HDIM];
    float kb[HDIM];
    float q[HDIM];
    float linW[2][HDIM];
    float linB[2];
};
__constant__ CParams cP;
__device__ CParams gStage;

// ---------------- scratch (static device globals; no allocation) -------------
// out: 4*N*8 fp16 (12.8MB) followed by den: 4*N fp32 (3.2MB), one memset
#define OUT_BYTES (4 * (size_t)N_NODES * HDIM * 2)
#define DEN_BYTES (4 * (size_t)N_NODES * 4)
__device__ __align__(16) char g_accbuf[OUT_BYTES + DEN_BYTES];
__device__ char  g_pack[4][(size_t)N_NODES * ROWB]; // per edge type: packed src rows
__device__ float g_ad[4 * N_NODES];                 // per edge type: dst alpha
__device__ float g_score[4];

__device__ __forceinline__ float fast_tanh(float x)
{
    float y;
    asm("tanh.approx.f32 %0, %1;" : "=f"(y) : "f"(x));
    return y;
}

// ---------------- parameter gather (one block) --------------------------------
struct SrcPtrs { const float* p[21]; };

__global__ void gather_kernel(SrcPtrs S)
{
    const int len[21] = {512,512,512, 8,8,8, 8,8,8,8, 8,8,8,8, 64,8,8, 8,8, 1,1};
    float* dst = reinterpret_cast<float*>(&gStage);
    int off = 0;
    for (int s = 0; s < 21; s++) {
        const float* src = S.p[s];
        for (int i = threadIdx.x; i < len[s]; i += blockDim.x)
            dst[off + i] = src[i];
        off += len[s];
    }
    if (threadIdx.x < 4) g_score[threadIdx.x] = 0.f;
}

// ---------------- fused projection (all 3 node types, grid.y) ----------------
// 1 thread = 1 node; register streaming, no smem.
struct ProjCfg {
    const float* x[3];
    char* pack0[3]; int asrc0[3];
    char* pack1[3]; int asrc1[3];
    float* ad0[3];  int adst0[3];
    float* ad1[3];  int adst1[3];
};

__device__ __forceinline__ void write_pack(char* pack, size_t gn,
                                           const float* acc, const float* att)
{
    __half2 hh[4];
#pragma unroll
    for (int i = 0; i < 4; i++) hh[i] = __floats2half2_rn(acc[2 * i], acc[2 * i + 1]);
    char* row = pack + gn * ROWB;
    *reinterpret_cast<uint4*>(row) = *reinterpret_cast<uint4*>(hh);
    float as = 0.f;
#pragma unroll
    for (int j = 0; j < HDIM; j++) as += acc[j] * att[j];
    *reinterpret_cast<float*>(row + 16) = as;
}

__global__ __launch_bounds__(256) void proj_kernel(ProjCfg C)
{
    int ty = blockIdx.y;
    size_t gn = (size_t)blockIdx.x * 256 + threadIdx.x;
    if (gn >= N_NODES) return;

    const float4* xr = reinterpret_cast<const float4*>(C.x[ty] + gn * FIN);
    const float* W = cP.W[ty];
    float acc[HDIM];
#pragma unroll
    for (int j = 0; j < HDIM; j++) acc[j] = cP.b[ty][j];
#pragma unroll
    for (int k4 = 0; k4 < 16; k4++) {
        float4 xv = __ldcs(xr + k4);
#pragma unroll
        for (int j = 0; j < HDIM; j++) {
            acc[j] += xv.x * W[(4 * k4 + 0) * HDIM + j]
                    + xv.y * W[(4 * k4 + 1) * HDIM + j]
                    + xv.z * W[(4 * k4 + 2) * HDIM + j]
                    + xv.w * W[(4 * k4 + 3) * HDIM + j];
        }
    }

    if (C.pack0[ty]) write_pack(C.pack0[ty], gn, acc, cP.attSrc[C.asrc0[ty]]);
    if (C.pack1[ty]) write_pack(C.pack1[ty], gn, acc, cP.attSrc[C.asrc1[ty]]);
    if (C.ad0[ty]) {
        const float* att = cP.attDst[C.adst0[ty]];
        float v = 0.f;
#pragma unroll
        for (int j = 0; j < HDIM; j++) v += acc[j] * att[j];
        C.ad0[ty][gn] = v;
    }
    if (C.ad1[ty]) {
        const float* att = cP.attDst[C.adst1[ty]];
        float v = 0.f;
#pragma unroll
        for (int j = 0; j < HDIM; j++) v += acc[j] * att[j];
        C.ad1[ty][gn] = v;
    }
}

// ---------------- fused edge pass (all 4 edge types, grid.y) -----------------
struct EdgeAll {
    const int*  ei[4];
    const char* pack[4];
    const float* ad[4];
    float* den[4];
    __half* out[4];
    int E[4];
};

__device__ __forceinline__ void edge_one(int r, int c,
                                         const char* __restrict__ pack,
                                         const float* __restrict__ ad,
                                         float* __restrict__ den,
                                         __half* __restrict__ out)
{
    const uint4* rowp = reinterpret_cast<const uint4*>(pack + (size_t)r * ROWB);
    uint4 hv = __ldg(rowp);                                      // 8 fp16 h
    float asv = __ldg(reinterpret_cast<const float*>(rowp) + 4); // same 32B sector
    float a = asv + __ldg(&ad[c]);
    a = (a > 0.f) ? a : 0.2f * a;
    float ex = __expf(a);

    const __half2* hp = reinterpret_cast<const __half2*>(&hv);
    float2 f0 = __half22float2(hp[0]);
    float2 f1 = __half22float2(hp[1]);
    float2 f2 = __half22float2(hp[2]);
    float2 f3 = __half22float2(hp[3]);

    // products in fp32, single rounding to fp16, one 16B vector red
    __half2 m0 = __floats2half2_rn(f0.x * ex, f0.y * ex);
    __half2 m1 = __floats2half2_rn(f1.x * ex, f1.y * ex);
    __half2 m2 = __floats2half2_rn(f2.x * ex, f2.y * ex);
    __half2 m3 = __floats2half2_rn(f3.x * ex, f3.y * ex);

    __half* op = out + (size_t)c * HDIM;
    asm volatile("red.global.add.noftz.v4.f16x2 [%0], {%1, %2, %3, %4};"
                 :: "l"(op),
                    "r"(*reinterpret_cast<unsigned*>(&m0)),
                    "r"(*reinterpret_cast<unsigned*>(&m1)),
                    "r"(*reinterpret_cast<unsigned*>(&m2)),
                    "r"(*reinterpret_cast<unsigned*>(&m3))
                 : "memory");
    atomicAdd(&den[c], ex);
}

__global__ void edge_kernel(EdgeAll A)
{
    int t = blockIdx.y;
    int E = A.E[t];
    const int*  ei   = A.ei[t];
    const char* pack = A.pack[t];
    const float* ad  = A.ad[t];
    float* den = A.den[t];
    __half* out = A.out[t];

    int i0 = (blockIdx.x * blockDim.x + threadIdx.x) * 4;
    if (i0 + 4 <= E) {
        int4 rr = __ldcs(reinterpret_cast<const int4*>(ei + i0));
        int4 cc = __ldcs(reinterpret_cast<const int4*>(ei + E + i0));
        edge_one(rr.x, cc.x, pack, ad, den, out);
        edge_one(rr.y, cc.y, pack, ad, den, out);
        edge_one(rr.z, cc.z, pack, ad, den, out);
        edge_one(rr.w, cc.w, pack, ad, den, out);
    } else {
        for (int i = i0; i < E; i++)
            edge_one(ei[i], ei[E + i], pack, ad, den, out);
    }
}

// ---------------- semantic score (all 4 metapaths, grid.y); inv inline -------
__global__ void score_kernel(const __half* __restrict__ out_base,
                             const float* __restrict__ den_base,
                             float* __restrict__ score)
{
    int g = blockIdx.y;
    const __half* o = out_base + (size_t)g * N_NODES * HDIM;
    const float* den = den_base + (size_t)g * N_NODES;
    int n = blockIdx.x * blockDim.x + threadIdx.x;
    float s = 0.f;
    if (n < N_NODES) {
        float inv = 1.f / (__ldg(&den[n]) + 1e-16f);
        uint4 hv = __ldg(reinterpret_cast<const uint4*>(o + (size_t)n * HDIM));
        const __half2* hp = reinterpret_cast<const __half2*>(&hv);
        float2 f0 = __half22float2(hp[0]);
        float2 f1 = __half22float2(hp[1]);
        float2 f2 = __half22float2(hp[2]);
        float2 f3 = __half22float2(hp[3]);
        float orl[HDIM];
        orl[0] = fmaxf(f0.x * inv, 0.f); orl[1] = fmaxf(f0.y * inv, 0.f);
        orl[2] = fmaxf(f1.x * inv, 0.f); orl[3] = fmaxf(f1.y * inv, 0.f);
        orl[4] = fmaxf(f2.x * inv, 0.f); orl[5] = fmaxf(f2.y * inv, 0.f);
        orl[6] = fmaxf(f3.x * inv, 0.f); orl[7] = fmaxf(f3.y * inv, 0.f);
#pragma unroll
        for (int j = 0; j < HDIM; j++) {
            float acc = cP.kb[j];
#pragma unroll
            for (int k = 0; k < HDIM; k++) acc += orl[k] * cP.kW[k * HDIM + j];
            s += cP.q[j] * fast_tanh(acc);
        }
    }
#pragma unroll
    for (int off = 16; off; off >>= 1) s += __shfl_xor_sync(0xffffffffu, s, off);
    __shared__ float ws[8];
    int lane = threadIdx.x & 31, wid = threadIdx.x >> 5;
    if (lane == 0) ws[wid] = s;
    __syncthreads();
    if (wid == 0) {
        s = (lane < 8) ? ws[lane] : 0.f;
#pragma unroll
        for (int off = 4; off; off >>= 1) s += __shfl_xor_sync(0xffffffffu, s, off);
        if (lane == 0) atomicAdd(&score[g], s);
    }
}

// ---------------- final heads (both groups, grid.y); attn softmax inline -----
__global__ void final_kernel(const __half* __restrict__ out_base,
                             const float* __restrict__ den_base,
                             const float* __restrict__ score,
                             float* __restrict__ pred)
{
    int g = blockIdx.y;   // 0: ind (types 0,1), 1: org (types 2,3)
    int n = blockIdx.x * blockDim.x + threadIdx.x;
    if (n >= N_NODES) return;

    float s0 = __ldg(&score[2 * g])     * (1.f / (float)N_NODES);
    float s1 = __ldg(&score[2 * g + 1]) * (1.f / (float)N_NODES);
    float m  = fmaxf(s0, s1);
    float e0 = __expf(s0 - m), e1 = __expf(s1 - m);
    float winv = 1.f / (e0 + e1);
    float w0 = e0 * winv, w1 = e1 * winv;

    const __half* o0 = out_base + (size_t)(2 * g)     * N_NODES * HDIM;
    const __half* o1 = out_base + (size_t)(2 * g + 1) * N_NODES * HDIM;
    float i0 = 1.f / (__ldg(&den_base[(size_t)(2 * g)     * N_NODES + n]) + 1e-16f);
    float i1 = 1.f / (__ldg(&den_base[(size_t)(2 * g + 1) * N_NODES + n]) + 1e-16f);

    uint4 hv0 = __ldg(reinterpret_cast<const uint4*>(o0 + (size_t)n * HDIM));
    uint4 hv1 = __ldg(reinterpret_cast<const uint4*>(o1 + (size_t)n * HDIM));
    const __half2* hp0 = reinterpret_cast<const __half2*>(&hv0);
    const __half2* hp1 = reinterpret_cast<const __half2*>(&hv1);

    float s = cP.linB[g];
#pragma unroll
    for (int p = 0; p < 4; p++) {
        float2 a = __half22float2(hp0[p]);
        float2 b = __half22float2(hp1[p]);
        float z0 = w0 * fmaxf(a.x * i0, 0.f) + w1 * fmaxf(b.x * i1, 0.f);
        float z1 = w0 * fmaxf(a.y * i0, 0.f) + w1 * fmaxf(b.y * i1, 0.f);
        s += z0 * cP.linW[g][2 * p] + z1 * cP.linW[g][2 * p + 1];
    }
    pred[(size_t)g * N_NODES + n] = 1.f / (1.f + __expf(-s));
}

// -----------------------------------------------------------------------------
extern "C" void kernel_launch(void* const* d_in, const int* in_sizes, int n_in,
                              void* d_out, int out_size)
{
    char *p_pack, *p_accbuf; float *p_ad, *p_score;
    cudaGetSymbolAddress((void**)&p_pack, g_pack);
    cudaGetSymbolAddress((void**)&p_accbuf, g_accbuf);
    cudaGetSymbolAddress((void**)&p_ad, g_ad);
    cudaGetSymbolAddress((void**)&p_score, g_score);
    void *a_cP, *a_stage;
    cudaGetSymbolAddress(&a_cP, cP);
    cudaGetSymbolAddress(&a_stage, gStage);

    __half* p_out = reinterpret_cast<__half*>(p_accbuf);
    float*  p_den = reinterpret_cast<float*>(p_accbuf + OUT_BYTES);

    char* pk[4];
    for (int t = 0; t < 4; t++) pk[t] = p_pack + (size_t)t * N_NODES * ROWB;

    // ---- params: gather into staging, then ONE copy into constant bank ----
    SrcPtrs SP;
    SP.p[0]  = (const float*)d_in[7];   // W_ind
    SP.p[1]  = (const float*)d_in[9];   // W_org
    SP.p[2]  = (const float*)d_in[11];  // W_ext
    SP.p[3]  = (const float*)d_in[8];   // b_ind
    SP.p[4]  = (const float*)d_in[10];  // b_org
    SP.p[5]  = (const float*)d_in[12];  // b_ext
    // attSrc, edge types t0=org->ind, t1=ext->ind, t2=ind->org, t3=ext->org
    SP.p[6]  = (const float*)d_in[15];
    SP.p[7]  = (const float*)d_in[17];
    SP.p[8]  = (const float*)d_in[13];
    SP.p[9]  = (const float*)d_in[19];
    // attDst
    SP.p[10] = (const float*)d_in[16];
    SP.p[11] = (const float*)d_in[18];
    SP.p[12] = (const float*)d_in[14];
    SP.p[13] = (const float*)d_in[20];
    SP.p[14] = (const float*)d_in[21];  // kW
    SP.p[15] = (const float*)d_in[22];  // kb
    SP.p[16] = (const float*)d_in[23];  // q
    SP.p[17] = (const float*)d_in[24];  // lin_ind_W
    SP.p[18] = (const float*)d_in[26];  // lin_org_W
    SP.p[19] = (const float*)d_in[25];  // lin_ind_b
    SP.p[20] = (const float*)d_in[27];  // lin_org_b
    gather_kernel<<<1, 256>>>(SP);
    cudaMemcpyAsync(a_cP, a_stage, sizeof(CParams), cudaMemcpyDeviceToDevice, 0);

    cudaMemsetAsync(p_accbuf, 0, OUT_BYTES + DEN_BYTES, 0);

    // ---- projection ----
    ProjCfg PC;
    PC.x[0] = (const float*)d_in[0];
    PC.x[1] = (const float*)d_in[1];
    PC.x[2] = (const float*)d_in[2];
    PC.pack0[0] = pk[2]; PC.asrc0[0] = 2;  PC.pack1[0] = nullptr; PC.asrc1[0] = 0;
    PC.ad0[0] = p_ad + 0 * N_NODES; PC.adst0[0] = 0;
    PC.ad1[0] = p_ad + 1 * N_NODES; PC.adst1[0] = 1;
    PC.pack0[1] = pk[0]; PC.asrc0[1] = 0;  PC.pack1[1] = nullptr; PC.asrc1[1] = 0;
    PC.ad0[1] = p_ad + 2 * N_NODES; PC.adst0[1] = 2;
    PC.ad1[1] = p_ad + 3 * N_NODES; PC.adst1[1] = 3;
    PC.pack0[2] = pk[1]; PC.asrc0[2] = 1;  PC.pack1[2] = pk[3]; PC.asrc1[2] = 3;
    PC.ad0[2] = nullptr; PC.adst0[2] = 0;
    PC.ad1[2] = nullptr; PC.adst1[2] = 0;

    dim3 pg((N_NODES + 255) / 256, 3);
    proj_kernel<<<pg, 256>>>(PC);

    // ---- edges ----
    EdgeAll EA;
    EA.ei[0] = (const int*)d_in[4]; EA.E[0] = in_sizes[4] / 2;  // org->ind
    EA.ei[1] = (const int*)d_in[5]; EA.E[1] = in_sizes[5] / 2;  // ext->ind
    EA.ei[2] = (const int*)d_in[3]; EA.E[2] = in_sizes[3] / 2;  // ind->org
    EA.ei[3] = (const int*)d_in[6]; EA.E[3] = in_sizes[6] / 2;  // ext->org
    int Emax = 0;
    for (int t = 0; t < 4; t++) {
        EA.pack[t] = pk[t];
        EA.ad[t]   = p_ad + (size_t)t * N_NODES;
        EA.den[t]  = p_den + (size_t)t * N_NODES;
        EA.out[t]  = p_out + (size_t)t * N_NODES * HDIM;
        if (EA.E[t] > Emax) Emax = EA.E[t];
    }
    dim3 eg((Emax / 4 + 255) / 256 + 1, 4);
    edge_kernel<<<eg, 256>>>(EA);

    // ---- semantic attention + heads ----
    const int NG = (N_NODES + 255) / 256;
    dim3 sg(NG, 4);
    score_kernel<<<sg, 256>>>(p_out, p_den, p_score);

    dim3 fg(NG, 2);
    final_kernel<<<fg, 256>>>(p_out, p_den, p_score, (float*)d_out);
}

// round 9
// speedup vs baseline: 1.0409x; 1.0409x over previous
#include <cuda_runtime.h>
#include <cuda_fp16.h>
#include <math.h>

#define N_NODES 200000
#define HDIM 8
#define FIN 64
#define ROWB 32     // packed src row: 16B fp16 h + 4B fp32 as + 12B pad
#define PNODES 160  // nodes per proj block (200000 % 160 == 0)

// ---------------- packed parameter block (constant + staging) ----------------
struct CParams {               // field order == gather segment order (all float)
    float W[3][FIN * HDIM];    // 3 x 512
    float b[3][HDIM];
    float attSrc[4][HDIM];     // t0..t3
    float attDst[4][HDIM];
    float kW[HDIM * HDIM];
    float kb[HDIM];
    float q[HDIM];
    float linW[2][HDIM];
    float linB[2];
};
__constant__ CParams cP;
__device__ CParams gStage;

// ---------------- scratch (static device globals; no allocation) -------------
// out: 4*N*8 fp16 (12.8MB) followed by den: 4*N fp32 (3.2MB), one memset
#define OUT_BYTES (4 * (size_t)N_NODES * HDIM * 2)
#define DEN_BYTES (4 * (size_t)N_NODES * 4)
__device__ __align__(16) char g_accbuf[OUT_BYTES + DEN_BYTES];
__device__ char  g_pack[4][(size_t)N_NODES * ROWB]; // per edge type: packed src rows
__device__ float g_ad[4 * N_NODES];                 // per edge type: dst alpha
__device__ float g_score[4];

__device__ __forceinline__ float fast_tanh(float x)
{
    float y;
    asm("tanh.approx.f32 %0, %1;" : "=f"(y) : "f"(x));
    return y;
}

// ---------------- parameter gather (one block) --------------------------------
struct SrcPtrs { const float* p[21]; };

__global__ void gather_kernel(SrcPtrs S)
{
    const int len[21] = {512,512,512, 8,8,8, 8,8,8,8, 8,8,8,8, 64,8,8, 8,8, 1,1};
    float* dst = reinterpret_cast<float*>(&gStage);
    int off = 0;
    for (int s = 0; s < 21; s++) {
        const float* src = S.p[s];
        for (int i = threadIdx.x; i < len[s]; i += blockDim.x)
            dst[off + i] = src[i];
        off += len[s];
    }
    if (threadIdx.x < 4) g_score[threadIdx.x] = 0.f;
}

// ---------------- fused projection (all 3 node types, grid.y) ----------------
// smem-staged coalesced loads (R7 layout — verified fast), params from constant.
struct ProjCfg {
    const float* x[3];
    char* pack0[3]; int asrc0[3];
    char* pack1[3]; int asrc1[3];
    float* ad0[3];  int adst0[3];
    float* ad1[3];  int adst1[3];
};

__device__ __forceinline__ void write_pack(char* pack, size_t gn,
                                           const float* acc, const float* att)
{
    __half2 hh[4];
#pragma unroll
    for (int i = 0; i < 4; i++) hh[i] = __floats2half2_rn(acc[2 * i], acc[2 * i + 1]);
    char* row = pack + gn * ROWB;
    *reinterpret_cast<uint4*>(row) = *reinterpret_cast<uint4*>(hh);
    float as = 0.f;
#pragma unroll
    for (int j = 0; j < HDIM; j++) as += acc[j] * att[j];
    *reinterpret_cast<float*>(row + 16) = as;
}

__global__ __launch_bounds__(PNODES) void proj_kernel(ProjCfg C)
{
    int ty = blockIdx.y;
    const float* x = C.x[ty];
    __shared__ float4 sx[PNODES * 17];   // stride-17 float4: conflict-free
    int tid = threadIdx.x;
    size_t base = (size_t)blockIdx.x * PNODES;

    const float4* xg = reinterpret_cast<const float4*>(x + base * FIN);
#pragma unroll 4
    for (int i = tid; i < PNODES * 16; i += PNODES) {
        int row = i >> 4, k4 = i & 15;
        sx[row * 17 + k4] = __ldcs(xg + i);
    }
    __syncthreads();

    const float* W = cP.W[ty];
    float acc[HDIM];
#pragma unroll
    for (int j = 0; j < HDIM; j++) acc[j] = cP.b[ty][j];
#pragma unroll
    for (int k4 = 0; k4 < 16; k4++) {
        float4 xv = sx[tid * 17 + k4];
#pragma unroll
        for (int j = 0; j < HDIM; j++) {
            acc[j] += xv.x * W[(4 * k4 + 0) * HDIM + j]
                    + xv.y * W[(4 * k4 + 1) * HDIM + j]
                    + xv.z * W[(4 * k4 + 2) * HDIM + j]
                    + xv.w * W[(4 * k4 + 3) * HDIM + j];
        }
    }

    size_t gn = base + tid;
    if (C.pack0[ty]) write_pack(C.pack0[ty], gn, acc, cP.attSrc[C.asrc0[ty]]);
    if (C.pack1[ty]) write_pack(C.pack1[ty], gn, acc, cP.attSrc[C.asrc1[ty]]);
    if (C.ad0[ty]) {
        const float* att = cP.attDst[C.adst0[ty]];
        float v = 0.f;
#pragma unroll
        for (int j = 0; j < HDIM; j++) v += acc[j] * att[j];
        C.ad0[ty][gn] = v;
    }
    if (C.ad1[ty]) {
        const float* att = cP.attDst[C.adst1[ty]];
        float v = 0.f;
#pragma unroll
        for (int j = 0; j < HDIM; j++) v += acc[j] * att[j];
        C.ad1[ty][gn] = v;
    }
}

// ---------------- fused edge pass (all 4 edge types, grid.y) -----------------
struct EdgeAll {
    const int*  ei[4];
    const char* pack[4];
    const float* ad[4];
    float* den[4];
    __half* out[4];
    int E[4];
};

__device__ __forceinline__ void edge_one(int r, int c,
                                         const char* __restrict__ pack,
                                         const float* __restrict__ ad,
                                         float* __restrict__ den,
                                         __half* __restrict__ out)
{
    const uint4* rowp = reinterpret_cast<const uint4*>(pack + (size_t)r * ROWB);
    uint4 hv = __ldg(rowp);                                      // 8 fp16 h
    float asv = __ldg(reinterpret_cast<const float*>(rowp) + 4); // same 32B sector
    float a = asv + __ldg(&ad[c]);
    a = (a > 0.f) ? a : 0.2f * a;
    float ex = __expf(a);

    const __half2* hp = reinterpret_cast<const __half2*>(&hv);
    float2 f0 = __half22float2(hp[0]);
    float2 f1 = __half22float2(hp[1]);
    float2 f2 = __half22float2(hp[2]);
    float2 f3 = __half22float2(hp[3]);

    // products in fp32, single rounding to fp16, one 16B vector red
    __half2 m0 = __floats2half2_rn(f0.x * ex, f0.y * ex);
    __half2 m1 = __floats2half2_rn(f1.x * ex, f1.y * ex);
    __half2 m2 = __floats2half2_rn(f2.x * ex, f2.y * ex);
    __half2 m3 = __floats2half2_rn(f3.x * ex, f3.y * ex);

    __half* op = out + (size_t)c * HDIM;
    asm volatile("red.global.add.noftz.v4.f16x2 [%0], {%1, %2, %3, %4};"
                 :: "l"(op),
                    "r"(*reinterpret_cast<unsigned*>(&m0)),
                    "r"(*reinterpret_cast<unsigned*>(&m1)),
                    "r"(*reinterpret_cast<unsigned*>(&m2)),
                    "r"(*reinterpret_cast<unsigned*>(&m3))
                 : "memory");
    atomicAdd(&den[c], ex);
}

__global__ void edge_kernel(EdgeAll A)
{
    int t = blockIdx.y;
    int E = A.E[t];
    const int*  ei   = A.ei[t];
    const char* pack = A.pack[t];
    const float* ad  = A.ad[t];
    float* den = A.den[t];
    __half* out = A.out[t];

    int i0 = (blockIdx.x * blockDim.x + threadIdx.x) * 8;
    if (i0 + 8 <= E) {
        int4 r0 = __ldcs(reinterpret_cast<const int4*>(ei + i0));
        int4 r1 = __ldcs(reinterpret_cast<const int4*>(ei + i0 + 4));
        int4 c0 = __ldcs(reinterpret_cast<const int4*>(ei + E + i0));
        int4 c1 = __ldcs(reinterpret_cast<const int4*>(ei + E + i0 + 4));
        edge_one(r0.x, c0.x, pack, ad, den, out);
        edge_one(r0.y, c0.y, pack, ad, den, out);
        edge_one(r0.z, c0.z, pack, ad, den, out);
        edge_one(r0.w, c0.w, pack, ad, den, out);
        edge_one(r1.x, c1.x, pack, ad, den, out);
        edge_one(r1.y, c1.y, pack, ad, den, out);
        edge_one(r1.z, c1.z, pack, ad, den, out);
        edge_one(r1.w, c1.w, pack, ad, den, out);
    } else {
        for (int i = i0; i < E; i++)
            edge_one(ei[i], ei[E + i], pack, ad, den, out);
    }
}

// ---------------- semantic score (all 4 metapaths, grid.y); inv inline -------
__global__ void score_kernel(const __half* __restrict__ out_base,
                             const float* __restrict__ den_base,
                             float* __restrict__ score)
{
    int g = blockIdx.y;
    const __half* o = out_base + (size_t)g * N_NODES * HDIM;
    const float* den = den_base + (size_t)g * N_NODES;
    int n = blockIdx.x * blockDim.x + threadIdx.x;
    float s = 0.f;
    if (n < N_NODES) {
        float inv = 1.f / (__ldg(&den[n]) + 1e-16f);
        uint4 hv = __ldg(reinterpret_cast<const uint4*>(o + (size_t)n * HDIM));
        const __half2* hp = reinterpret_cast<const __half2*>(&hv);
        float2 f0 = __half22float2(hp[0]);
        float2 f1 = __half22float2(hp[1]);
        float2 f2 = __half22float2(hp[2]);
        float2 f3 = __half22float2(hp[3]);
        float orl[HDIM];
        orl[0] = fmaxf(f0.x * inv, 0.f); orl[1] = fmaxf(f0.y * inv, 0.f);
        orl[2] = fmaxf(f1.x * inv, 0.f); orl[3] = fmaxf(f1.y * inv, 0.f);
        orl[4] = fmaxf(f2.x * inv, 0.f); orl[5] = fmaxf(f2.y * inv, 0.f);
        orl[6] = fmaxf(f3.x * inv, 0.f); orl[7] = fmaxf(f3.y * inv, 0.f);
#pragma unroll
        for (int j = 0; j < HDIM; j++) {
            float acc = cP.kb[j];
#pragma unroll
            for (int k = 0; k < HDIM; k++) acc += orl[k] * cP.kW[k * HDIM + j];
            s += cP.q[j] * fast_tanh(acc);
        }
    }
#pragma unroll
    for (int off = 16; off; off >>= 1) s += __shfl_xor_sync(0xffffffffu, s, off);
    __shared__ float ws[8];
    int lane = threadIdx.x & 31, wid = threadIdx.x >> 5;
    if (lane == 0) ws[wid] = s;
    __syncthreads();
    if (wid == 0) {
        s = (lane < 8) ? ws[lane] : 0.f;
#pragma unroll
        for (int off = 4; off; off >>= 1) s += __shfl_xor_sync(0xffffffffu, s, off);
        if (lane == 0) atomicAdd(&score[g], s);
    }
}

// ---------------- final heads (both groups, grid.y); attn softmax inline -----
__global__ void final_kernel(const __half* __restrict__ out_base,
                             const float* __restrict__ den_base,
                             const float* __restrict__ score,
                             float* __restrict__ pred)
{
    int g = blockIdx.y;   // 0: ind (types 0,1), 1: org (types 2,3)
    int n = blockIdx.x * blockDim.x + threadIdx.x;
    if (n >= N_NODES) return;

    float s0 = __ldg(&score[2 * g])     * (1.f / (float)N_NODES);
    float s1 = __ldg(&score[2 * g + 1]) * (1.f / (float)N_NODES);
    float m  = fmaxf(s0, s1);
    float e0 = __expf(s0 - m), e1 = __expf(s1 - m);
    float winv = 1.f / (e0 + e1);
    float w0 = e0 * winv, w1 = e1 * winv;

    const __half* o0 = out_base + (size_t)(2 * g)     * N_NODES * HDIM;
    const __half* o1 = out_base + (size_t)(2 * g + 1) * N_NODES * HDIM;
    float i0 = 1.f / (__ldg(&den_base[(size_t)(2 * g)     * N_NODES + n]) + 1e-16f);
    float i1 = 1.f / (__ldg(&den_base[(size_t)(2 * g + 1) * N_NODES + n]) + 1e-16f);

    uint4 hv0 = __ldg(reinterpret_cast<const uint4*>(o0 + (size_t)n * HDIM));
    uint4 hv1 = __ldg(reinterpret_cast<const uint4*>(o1 + (size_t)n * HDIM));
    const __half2* hp0 = reinterpret_cast<const __half2*>(&hv0);
    const __half2* hp1 = reinterpret_cast<const __half2*>(&hv1);

    float s = cP.linB[g];
#pragma unroll
    for (int p = 0; p < 4; p++) {
        float2 a = __half22float2(hp0[p]);
        float2 b = __half22float2(hp1[p]);
        float z0 = w0 * fmaxf(a.x * i0, 0.f) + w1 * fmaxf(b.x * i1, 0.f);
        float z1 = w0 * fmaxf(a.y * i0, 0.f) + w1 * fmaxf(b.y * i1, 0.f);
        s += z0 * cP.linW[g][2 * p] + z1 * cP.linW[g][2 * p + 1];
    }
    pred[(size_t)g * N_NODES + n] = 1.f / (1.f + __expf(-s));
}

// -----------------------------------------------------------------------------
extern "C" void kernel_launch(void* const* d_in, const int* in_sizes, int n_in,
                              void* d_out, int out_size)
{
    char *p_pack, *p_accbuf; float *p_ad, *p_score;
    cudaGetSymbolAddress((void**)&p_pack, g_pack);
    cudaGetSymbolAddress((void**)&p_accbuf, g_accbuf);
    cudaGetSymbolAddress((void**)&p_ad, g_ad);
    cudaGetSymbolAddress((void**)&p_score, g_score);
    void *a_cP, *a_stage;
    cudaGetSymbolAddress(&a_cP, cP);
    cudaGetSymbolAddress(&a_stage, gStage);

    __half* p_out = reinterpret_cast<__half*>(p_accbuf);
    float*  p_den = reinterpret_cast<float*>(p_accbuf + OUT_BYTES);

    char* pk[4];
    for (int t = 0; t < 4; t++) pk[t] = p_pack + (size_t)t * N_NODES * ROWB;

    // ---- params: gather into staging, then ONE copy into constant bank ----
    SrcPtrs SP;
    SP.p[0]  = (const float*)d_in[7];   // W_ind
    SP.p[1]  = (const float*)d_in[9];   // W_org
    SP.p[2]  = (const float*)d_in[11];  // W_ext
    SP.p[3]  = (const float*)d_in[8];   // b_ind
    SP.p[4]  = (const float*)d_in[10];  // b_org
    SP.p[5]  = (const float*)d_in[12];  // b_ext
    // attSrc, edge types t0=org->ind, t1=ext->ind, t2=ind->org, t3=ext->org
    SP.p[6]  = (const float*)d_in[15];
    SP.p[7]  = (const float*)d_in[17];
    SP.p[8]  = (const float*)d_in[13];
    SP.p[9]  = (const float*)d_in[19];
    // attDst
    SP.p[10] = (const float*)d_in[16];
    SP.p[11] = (const float*)d_in[18];
    SP.p[12] = (const float*)d_in[14];
    SP.p[13] = (const float*)d_in[20];
    SP.p[14] = (const float*)d_in[21];  // kW
    SP.p[15] = (const float*)d_in[22];  // kb
    SP.p[16] = (const float*)d_in[23];  // q
    SP.p[17] = (const float*)d_in[24];  // lin_ind_W
    SP.p[18] = (const float*)d_in[26];  // lin_org_W
    SP.p[19] = (const float*)d_in[25];  // lin_ind_b
    SP.p[20] = (const float*)d_in[27];  // lin_org_b
    gather_kernel<<<1, 256>>>(SP);
    cudaMemcpyAsync(a_cP, a_stage, sizeof(CParams), cudaMemcpyDeviceToDevice, 0);

    cudaMemsetAsync(p_accbuf, 0, OUT_BYTES + DEN_BYTES, 0);

    // ---- projection ----
    ProjCfg PC;
    PC.x[0] = (const float*)d_in[0];
    PC.x[1] = (const float*)d_in[1];
    PC.x[2] = (const float*)d_in[2];
    PC.pack0[0] = pk[2]; PC.asrc0[0] = 2;  PC.pack1[0] = nullptr; PC.asrc1[0] = 0;
    PC.ad0[0] = p_ad + 0 * N_NODES; PC.adst0[0] = 0;
    PC.ad1[0] = p_ad + 1 * N_NODES; PC.adst1[0] = 1;
    PC.pack0[1] = pk[0]; PC.asrc0[1] = 0;  PC.pack1[1] = nullptr; PC.asrc1[1] = 0;
    PC.ad0[1] = p_ad + 2 * N_NODES; PC.adst0[1] = 2;
    PC.ad1[1] = p_ad + 3 * N_NODES; PC.adst1[1] = 3;
    PC.pack0[2] = pk[1]; PC.asrc0[2] = 1;  PC.pack1[2] = pk[3]; PC.asrc1[2] = 3;
    PC.ad0[2] = nullptr; PC.adst0[2] = 0;
    PC.ad1[2] = nullptr; PC.adst1[2] = 0;

    dim3 pg(N_NODES / PNODES, 3);
    proj_kernel<<<pg, PNODES>>>(PC);

    // ---- edges ----
    EdgeAll EA;
    EA.ei[0] = (const int*)d_in[4]; EA.E[0] = in_sizes[4] / 2;  // org->ind
    EA.ei[1] = (const int*)d_in[5]; EA.E[1] = in_sizes[5] / 2;  // ext->ind
    EA.ei[2] = (const int*)d_in[3]; EA.E[2] = in_sizes[3] / 2;  // ind->org
    EA.ei[3] = (const int*)d_in[6]; EA.E[3] = in_sizes[6] / 2;  // ext->org
    int Emax = 0;
    for (int t = 0; t < 4; t++) {
        EA.pack[t] = pk[t];
        EA.ad[t]   = p_ad + (size_t)t * N_NODES;
        EA.den[t]  = p_den + (size_t)t * N_NODES;
        EA.out[t]  = p_out + (size_t)t * N_NODES * HDIM;
        if (EA.E[t] > Emax) Emax = EA.E[t];
    }
    dim3 eg((Emax / 8 + 255) / 256 + 1, 4);
    edge_kernel<<<eg, 256>>>(EA);

    // ---- semantic attention + heads ----
    const int NG = (N_NODES + 255) / 256;
    dim3 sg(NG, 4);
    score_kernel<<<sg, 256>>>(p_out, p_den, p_score);

    dim3 fg(NG, 2);
    final_kernel<<<fg, 256>>>(p_out, p_den, p_score, (float*)d_out);
}

// round 10
// speedup vs baseline: 1.1696x; 1.1236x over previous
#include <cuda_runtime.h>
#include <cuda_fp16.h>
#include <math.h>

#define N_NODES 200000
#define HDIM 8
#define FIN 64
#define PNODES 160  // nodes per proj block (200000 % 160 == 0)

// ---------------- packed parameter block (constant + staging) ----------------
struct CParams {               // field order == gather segment order (all float)
    float W[3][FIN * HDIM];    // 3 x 512
    float b[3][HDIM];
    float attSrc[4][HDIM];     // t0..t3
    float attDst[4][HDIM];
    float kW[HDIM * HDIM];
    float kb[HDIM];
    float q[HDIM];
    float linW[2][HDIM];
    float linB[2];
};
__constant__ CParams cP;
__device__ CParams gStage;

// ---------------- scratch (static device globals; no allocation) -------------
// out: 4*N*8 fp16 (12.8MB) followed by den: 4*N fp32 (3.2MB), one memset
#define OUT_BYTES (4 * (size_t)N_NODES * HDIM * 2)
#define DEN_BYTES (4 * (size_t)N_NODES * 4)
__device__ __align__(16) char g_accbuf[OUT_BYTES + DEN_BYTES];
__device__ __align__(16) __half g_hsrc[3][(size_t)N_NODES * HDIM]; // fp16 h per node type
__device__ float g_ad[4 * N_NODES];                 // per edge type: dst alpha
__device__ float g_score[4];

__device__ __forceinline__ float fast_tanh(float x)
{
    float y;
    asm("tanh.approx.f32 %0, %1;" : "=f"(y) : "f"(x));
    return y;
}

// ---------------- parameter gather (one block) --------------------------------
struct SrcPtrs { const float* p[21]; };

__global__ void gather_kernel(SrcPtrs S)
{
    const int len[21] = {512,512,512, 8,8,8, 8,8,8,8, 8,8,8,8, 64,8,8, 8,8, 1,1};
    float* dst = reinterpret_cast<float*>(&gStage);
    int off = 0;
    for (int s = 0; s < 21; s++) {
        const float* src = S.p[s];
        for (int i = threadIdx.x; i < len[s]; i += blockDim.x)
            dst[off + i] = src[i];
        off += len[s];
    }
    if (threadIdx.x < 4) g_score[threadIdx.x] = 0.f;
}

// ---------------- fused projection (all 3 node types, grid.y) ----------------
// smem-staged coalesced loads; h written as fp16 row; up to 2 dst alphas.
struct ProjCfg {
    const float* x[3];
    __half* hout[3];
    float* ad0[3];  int adst0[3];
    float* ad1[3];  int adst1[3];
};

__global__ __launch_bounds__(PNODES) void proj_kernel(ProjCfg C)
{
    int ty = blockIdx.y;
    const float* x = C.x[ty];
    __shared__ float4 sx[PNODES * 17];   // stride-17 float4: conflict-free
    int tid = threadIdx.x;
    size_t base = (size_t)blockIdx.x * PNODES;

    const float4* xg = reinterpret_cast<const float4*>(x + base * FIN);
#pragma unroll 4
    for (int i = tid; i < PNODES * 16; i += PNODES) {
        int row = i >> 4, k4 = i & 15;
        sx[row * 17 + k4] = __ldcs(xg + i);
    }
    __syncthreads();

    const float* W = cP.W[ty];
    float acc[HDIM];
#pragma unroll
    for (int j = 0; j < HDIM; j++) acc[j] = cP.b[ty][j];
#pragma unroll
    for (int k4 = 0; k4 < 16; k4++) {
        float4 xv = sx[tid * 17 + k4];
#pragma unroll
        for (int j = 0; j < HDIM; j++) {
            acc[j] += xv.x * W[(4 * k4 + 0) * HDIM + j]
                    + xv.y * W[(4 * k4 + 1) * HDIM + j]
                    + xv.z * W[(4 * k4 + 2) * HDIM + j]
                    + xv.w * W[(4 * k4 + 3) * HDIM + j];
        }
    }

    size_t gn = base + tid;
    // fp16 h row (16B)
    __half2 hh[4];
#pragma unroll
    for (int i = 0; i < 4; i++) hh[i] = __floats2half2_rn(acc[2 * i], acc[2 * i + 1]);
    *reinterpret_cast<uint4*>(C.hout[ty] + gn * HDIM) = *reinterpret_cast<uint4*>(hh);

    if (C.ad0[ty]) {
        const float* att = cP.attDst[C.adst0[ty]];
        float v = 0.f;
#pragma unroll
        for (int j = 0; j < HDIM; j++) v += acc[j] * att[j];
        C.ad0[ty][gn] = v;
    }
    if (C.ad1[ty]) {
        const float* att = cP.attDst[C.adst1[ty]];
        float v = 0.f;
#pragma unroll
        for (int j = 0; j < HDIM; j++) v += acc[j] * att[j];
        C.ad1[ty][gn] = v;
    }
}

// ---------------- fused edge pass (all 4 edge types, grid.y) -----------------
struct EdgeAll {
    const int*  ei[4];
    const __half* hsrc[4];
    const float* ad[4];
    float* den[4];
    __half* out[4];
    int E[4];
};

__device__ __forceinline__ void edge_one(int r, int c,
                                         const __half* __restrict__ hsrc,
                                         const float* __restrict__ attS,
                                         const float* __restrict__ ad,
                                         float* __restrict__ den,
                                         __half* __restrict__ out)
{
    uint4 hv = __ldg(reinterpret_cast<const uint4*>(hsrc + (size_t)r * HDIM)); // 8 fp16
    const __half2* hp = reinterpret_cast<const __half2*>(&hv);
    float2 f0 = __half22float2(hp[0]);
    float2 f1 = __half22float2(hp[1]);
    float2 f2 = __half22float2(hp[2]);
    float2 f3 = __half22float2(hp[3]);

    // recompute src alpha from gathered h (FMA pipe is idle; saves a wavefront)
    float asv = f0.x * attS[0] + f0.y * attS[1]
              + f1.x * attS[2] + f1.y * attS[3]
              + f2.x * attS[4] + f2.y * attS[5]
              + f3.x * attS[6] + f3.y * attS[7];

    float a = asv + __ldg(&ad[c]);
    a = (a > 0.f) ? a : 0.2f * a;
    float ex = __expf(a);

    // products in fp32, single rounding to fp16, one 16B vector red
    __half2 m0 = __floats2half2_rn(f0.x * ex, f0.y * ex);
    __half2 m1 = __floats2half2_rn(f1.x * ex, f1.y * ex);
    __half2 m2 = __floats2half2_rn(f2.x * ex, f2.y * ex);
    __half2 m3 = __floats2half2_rn(f3.x * ex, f3.y * ex);

    __half* op = out + (size_t)c * HDIM;
    asm volatile("red.global.add.noftz.v4.f16x2 [%0], {%1, %2, %3, %4};"
                 :: "l"(op),
                    "r"(*reinterpret_cast<unsigned*>(&m0)),
                    "r"(*reinterpret_cast<unsigned*>(&m1)),
                    "r"(*reinterpret_cast<unsigned*>(&m2)),
                    "r"(*reinterpret_cast<unsigned*>(&m3))
                 : "memory");
    atomicAdd(&den[c], ex);
}

__global__ void edge_kernel(EdgeAll A)
{
    int t = blockIdx.y;
    int E = A.E[t];
    const int*  ei  = A.ei[t];
    const __half* hsrc = A.hsrc[t];
    const float* ad = A.ad[t];
    float* den = A.den[t];
    __half* out = A.out[t];

    float attS[HDIM];
#pragma unroll
    for (int j = 0; j < HDIM; j++) attS[j] = cP.attSrc[t][j];

    int i0 = (blockIdx.x * blockDim.x + threadIdx.x) * 4;
    if (i0 + 4 <= E) {
        int4 rr = __ldcs(reinterpret_cast<const int4*>(ei + i0));
        int4 cc = __ldcs(reinterpret_cast<const int4*>(ei + E + i0));
        edge_one(rr.x, cc.x, hsrc, attS, ad, den, out);
        edge_one(rr.y, cc.y, hsrc, attS, ad, den, out);
        edge_one(rr.z, cc.z, hsrc, attS, ad, den, out);
        edge_one(rr.w, cc.w, hsrc, attS, ad, den, out);
    } else {
        for (int i = i0; i < E; i++)
            edge_one(ei[i], ei[E + i], hsrc, attS, ad, den, out);
    }
}

// ---------------- semantic score (all 4 metapaths, grid.y); inv inline -------
__global__ void score_kernel(const __half* __restrict__ out_base,
                             const float* __restrict__ den_base,
                             float* __restrict__ score)
{
    int g = blockIdx.y;
    const __half* o = out_base + (size_t)g * N_NODES * HDIM;
    const float* den = den_base + (size_t)g * N_NODES;
    int n = blockIdx.x * blockDim.x + threadIdx.x;
    float s = 0.f;
    if (n < N_NODES) {
        float inv = 1.f / (__ldg(&den[n]) + 1e-16f);
        uint4 hv = __ldg(reinterpret_cast<const uint4*>(o + (size_t)n * HDIM));
        const __half2* hp = reinterpret_cast<const __half2*>(&hv);
        float2 f0 = __half22float2(hp[0]);
        float2 f1 = __half22float2(hp[1]);
        float2 f2 = __half22float2(hp[2]);
        float2 f3 = __half22float2(hp[3]);
        float orl[HDIM];
        orl[0] = fmaxf(f0.x * inv, 0.f); orl[1] = fmaxf(f0.y * inv, 0.f);
        orl[2] = fmaxf(f1.x * inv, 0.f); orl[3] = fmaxf(f1.y * inv, 0.f);
        orl[4] = fmaxf(f2.x * inv, 0.f); orl[5] = fmaxf(f2.y * inv, 0.f);
        orl[6] = fmaxf(f3.x * inv, 0.f); orl[7] = fmaxf(f3.y * inv, 0.f);
#pragma unroll
        for (int j = 0; j < HDIM; j++) {
            float acc = cP.kb[j];
#pragma unroll
            for (int k = 0; k < HDIM; k++) acc += orl[k] * cP.kW[k * HDIM + j];
            s += cP.q[j] * fast_tanh(acc);
        }
    }
#pragma unroll
    for (int off = 16; off; off >>= 1) s += __shfl_xor_sync(0xffffffffu, s, off);
    __shared__ float ws[8];
    int lane = threadIdx.x & 31, wid = threadIdx.x >> 5;
    if (lane == 0) ws[wid] = s;
    __syncthreads();
    if (wid == 0) {
        s = (lane < 8) ? ws[lane] : 0.f;
#pragma unroll
        for (int off = 4; off; off >>= 1) s += __shfl_xor_sync(0xffffffffu, s, off);
        if (lane == 0) atomicAdd(&score[g], s);
    }
}

// ---------------- final heads (both groups, grid.y); attn softmax inline -----
__global__ void final_kernel(const __half* __restrict__ out_base,
                             const float* __restrict__ den_base,
                             const float* __restrict__ score,
                             float* __restrict__ pred)
{
    int g = blockIdx.y;   // 0: ind (types 0,1), 1: org (types 2,3)
    int n = blockIdx.x * blockDim.x + threadIdx.x;
    if (n >= N_NODES) return;

    float s0 = __ldg(&score[2 * g])     * (1.f / (float)N_NODES);
    float s1 = __ldg(&score[2 * g + 1]) * (1.f / (float)N_NODES);
    float m  = fmaxf(s0, s1);
    float e0 = __expf(s0 - m), e1 = __expf(s1 - m);
    float winv = 1.f / (e0 + e1);
    float w0 = e0 * winv, w1 = e1 * winv;

    const __half* o0 = out_base + (size_t)(2 * g)     * N_NODES * HDIM;
    const __half* o1 = out_base + (size_t)(2 * g + 1) * N_NODES * HDIM;
    float i0 = 1.f / (__ldg(&den_base[(size_t)(2 * g)     * N_NODES + n]) + 1e-16f);
    float i1 = 1.f / (__ldg(&den_base[(size_t)(2 * g + 1) * N_NODES + n]) + 1e-16f);

    uint4 hv0 = __ldg(reinterpret_cast<const uint4*>(o0 + (size_t)n * HDIM));
    uint4 hv1 = __ldg(reinterpret_cast<const uint4*>(o1 + (size_t)n * HDIM));
    const __half2* hp0 = reinterpret_cast<const __half2*>(&hv0);
    const __half2* hp1 = reinterpret_cast<const __half2*>(&hv1);

    float s = cP.linB[g];
#pragma unroll
    for (int p = 0; p < 4; p++) {
        float2 a = __half22float2(hp0[p]);
        float2 b = __half22float2(hp1[p]);
        float z0 = w0 * fmaxf(a.x * i0, 0.f) + w1 * fmaxf(b.x * i1, 0.f);
        float z1 = w0 * fmaxf(a.y * i0, 0.f) + w1 * fmaxf(b.y * i1, 0.f);
        s += z0 * cP.linW[g][2 * p] + z1 * cP.linW[g][2 * p + 1];
    }
    pred[(size_t)g * N_NODES + n] = 1.f / (1.f + __expf(-s));
}

// -----------------------------------------------------------------------------
extern "C" void kernel_launch(void* const* d_in, const int* in_sizes, int n_in,
                              void* d_out, int out_size)
{
    char *p_accbuf; __half* p_h; float *p_ad, *p_score;
    cudaGetSymbolAddress((void**)&p_accbuf, g_accbuf);
    cudaGetSymbolAddress((void**)&p_h, g_hsrc);
    cudaGetSymbolAddress((void**)&p_ad, g_ad);
    cudaGetSymbolAddress((void**)&p_score, g_score);
    void *a_cP, *a_stage;
    cudaGetSymbolAddress(&a_cP, cP);
    cudaGetSymbolAddress(&a_stage, gStage);

    __half* p_out = reinterpret_cast<__half*>(p_accbuf);
    float*  p_den = reinterpret_cast<float*>(p_accbuf + OUT_BYTES);

    __half* h_ind = p_h;
    __half* h_org = p_h + (size_t)N_NODES * HDIM;
    __half* h_ext = p_h + 2 * (size_t)N_NODES * HDIM;

    // ---- params: gather into staging, then ONE copy into constant bank ----
    SrcPtrs SP;
    SP.p[0]  = (const float*)d_in[7];   // W_ind
    SP.p[1]  = (const float*)d_in[9];   // W_org
    SP.p[2]  = (const float*)d_in[11];  // W_ext
    SP.p[3]  = (const float*)d_in[8];   // b_ind
    SP.p[4]  = (const float*)d_in[10];  // b_org
    SP.p[5]  = (const float*)d_in[12];  // b_ext
    // attSrc, edge types t0=org->ind, t1=ext->ind, t2=ind->org, t3=ext->org
    SP.p[6]  = (const float*)d_in[15];
    SP.p[7]  = (const float*)d_in[17];
    SP.p[8]  = (const float*)d_in[13];
    SP.p[9]  = (const float*)d_in[19];
    // attDst
    SP.p[10] = (const float*)d_in[16];
    SP.p[11] = (const float*)d_in[18];
    SP.p[12] = (const float*)d_in[14];
    SP.p[13] = (const float*)d_in[20];
    SP.p[14] = (const float*)d_in[21];  // kW
    SP.p[15] = (const float*)d_in[22];  // kb
    SP.p[16] = (const float*)d_in[23];  // q
    SP.p[17] = (const float*)d_in[24];  // lin_ind_W
    SP.p[18] = (const float*)d_in[26];  // lin_org_W
    SP.p[19] = (const float*)d_in[25];  // lin_ind_b
    SP.p[20] = (const float*)d_in[27];  // lin_org_b
    gather_kernel<<<1, 256>>>(SP);
    cudaMemcpyAsync(a_cP, a_stage, sizeof(CParams), cudaMemcpyDeviceToDevice, 0);

    cudaMemsetAsync(p_accbuf, 0, OUT_BYTES + DEN_BYTES, 0);

    // ---- projection ----
    ProjCfg PC;
    PC.x[0] = (const float*)d_in[0];  PC.hout[0] = h_ind;
    PC.x[1] = (const float*)d_in[1];  PC.hout[1] = h_org;
    PC.x[2] = (const float*)d_in[2];  PC.hout[2] = h_ext;
    // ind: dst alphas for t0 (org->ind), t1 (ext->ind)
    PC.ad0[0] = p_ad + 0 * N_NODES; PC.adst0[0] = 0;
    PC.ad1[0] = p_ad + 1 * N_NODES; PC.adst1[0] = 1;
    // org: dst alphas for t2 (ind->org), t3 (ext->org)
    PC.ad0[1] = p_ad + 2 * N_NODES; PC.adst0[1] = 2;
    PC.ad1[1] = p_ad + 3 * N_NODES; PC.adst1[1] = 3;
    // ext: no dst alphas
    PC.ad0[2] = nullptr; PC.adst0[2] = 0;
    PC.ad1[2] = nullptr; PC.adst1[2] = 0;

    dim3 pg(N_NODES / PNODES, 3);
    proj_kernel<<<pg, PNODES>>>(PC);

    // ---- edges ----
    EdgeAll EA;
    EA.ei[0] = (const int*)d_in[4]; EA.E[0] = in_sizes[4] / 2; EA.hsrc[0] = h_org; // org->ind
    EA.ei[1] = (const int*)d_in[5]; EA.E[1] = in_sizes[5] / 2; EA.hsrc[1] = h_ext; // ext->ind
    EA.ei[2] = (const int*)d_in[3]; EA.E[2] = in_sizes[3] / 2; EA.hsrc[2] = h_ind; // ind->org
    EA.ei[3] = (const int*)d_in[6]; EA.E[3] = in_sizes[6] / 2; EA.hsrc[3] = h_ext; // ext->org
    int Emax = 0;
    for (int t = 0; t < 4; t++) {
        EA.ad[t]   = p_ad + (size_t)t * N_NODES;
        EA.den[t]  = p_den + (size_t)t * N_NODES;
        EA.out[t]  = p_out + (size_t)t * N_NODES * HDIM;
        if (EA.E[t] > Emax) Emax = EA.E[t];
    }
    dim3 eg((Emax / 4 + 255) / 256 + 1, 4);
    edge_kernel<<<eg, 256>>>(EA);

    // ---- semantic attention + heads ----
    const int NG = (N_NODES + 255) / 256;
    dim3 sg(NG, 4);
    score_kernel<<<sg, 256>>>(p_out, p_den, p_score);

    dim3 fg(NG, 2);
    final_kernel<<<fg, 256>>>(p_out, p_den, p_score, (float*)d_out);
}